// round 3
// baseline (speedup 1.0000x reference)
#include <cuda_runtime.h>
#include <cstdint>

#define NROWS  512
#define INSIZE 512
#define KK     64
#define DD     16
#define MM     (KK * DD)        // 1024
#define OUTW   (INSIZE + KK)    // 576
#define BK     16

typedef unsigned long long ull;

// Scratch for feat = x @ W^T + b  (512 x 1024 fp32 = 2MB)
__device__ float g_feat[NROWS * MM];

// ---------------------------------------------------------------------------
// Packed f32x2 helpers
// ---------------------------------------------------------------------------
__device__ __forceinline__ ull addf32x2(ull a, ull b) {
    ull r;
    asm("add.rn.f32x2 %0, %1, %2;" : "=l"(r) : "l"(a), "l"(b));
    return r;
}
__device__ __forceinline__ ull fmaf32x2(ull a, ull b, ull c) {
    ull r;
    asm("fma.rn.f32x2 %0, %1, %2, %3;" : "=l"(r) : "l"(a), "l"(b), "l"(c));
    return r;
}
__device__ __forceinline__ ull pk2(float lo, float hi) {
    ull r;
    asm("mov.b64 %0, {%1, %2};" : "=l"(r)
        : "r"(__float_as_uint(lo)), "r"(__float_as_uint(hi)));
    return r;
}
__device__ __forceinline__ float lo32(ull v) {
    return __uint_as_float((unsigned int)v);
}
__device__ __forceinline__ float hi32(ull v) {
    return __uint_as_float((unsigned int)(v >> 32));
}

// ---------------------------------------------------------------------------
// Kernel 1: feat = x @ W^T + b  via packed FFMA2.
// 64x64 tile, 512 threads (16 warps -> 4 warps/SMSP), micro-tile 2 rows x 4 cols.
// x-tile duplicated in smem so one LDS.128 yields (r0,r0),(r1,r1).
// Double-buffered, one sync per BK step. Grid 128 blocks = one wave.
// ---------------------------------------------------------------------------
__global__ __launch_bounds__(512)
void gemm_kernel(const float* __restrict__ x, const float* __restrict__ W,
                 const float* __restrict__ b) {
    __shared__ __align__(16) float XsD[2][BK][128];  // duplicated rows: 16KB
    __shared__ __align__(16) float Ws [2][BK][64];   // 8KB

    const int bm = blockIdx.x * 64;   // feat col tile (W rows)
    const int bn = blockIdx.y * 64;   // feat row tile (x rows)
    const int tid = threadIdx.x;

    // loader mapping: first 256 threads load x tile, last 256 load W tile
    const bool isX = tid < 256;
    const int lt = tid & 255;
    const int lr = lt >> 2;           // 0..63
    const int lc = (lt & 3) * 4;      // 0,4,8,12
    const float* src = isX ? &x[(bn + lr) * INSIZE + lc]
                           : &W[(bm + lr) * INSIZE + lc];

    // compute mapping: 2 rows x 4 cols per thread
    const int tx = tid & 15;          // cols 4*tx..4*tx+3
    const int ty = tid >> 4;          // 0..31 -> rows 2*ty, 2*ty+1

    ull acc[2][2];
    acc[0][0] = acc[0][1] = acc[1][0] = acc[1][1] = 0ULL;

    int buf = 0;
    {
        float4 v = *(const float4*)src;
        float a[4] = {v.x, v.y, v.z, v.w};
        if (isX) {
#pragma unroll
            for (int q = 0; q < 4; q++)
                *(float2*)&XsD[buf][lc + q][2 * lr] = make_float2(a[q], a[q]);
        } else {
#pragma unroll
            for (int q = 0; q < 4; q++) Ws[buf][lc + q][lr] = a[q];
        }
    }
    __syncthreads();

    for (int k0 = BK; k0 <= INSIZE; k0 += BK) {
        const bool more = (k0 < INSIZE);
        float4 v2;
        if (more) v2 = *(const float4*)(src + k0);

#pragma unroll
        for (int kk = 0; kk < BK; kk++) {
            ulonglong2 xp = *(const ulonglong2*)&XsD[buf][kk][4 * ty];  // (r0,r0),(r1,r1)
            ulonglong2 wp = *(const ulonglong2*)&Ws [buf][kk][4 * tx];  // 2 col-pairs
            acc[0][0] = fmaf32x2(xp.x, wp.x, acc[0][0]);
            acc[0][1] = fmaf32x2(xp.x, wp.y, acc[0][1]);
            acc[1][0] = fmaf32x2(xp.y, wp.x, acc[1][0]);
            acc[1][1] = fmaf32x2(xp.y, wp.y, acc[1][1]);
        }

        if (more) {
            buf ^= 1;
            float a[4] = {v2.x, v2.y, v2.z, v2.w};
            if (isX) {
#pragma unroll
                for (int q = 0; q < 4; q++)
                    *(float2*)&XsD[buf][lc + q][2 * lr] = make_float2(a[q], a[q]);
            } else {
#pragma unroll
                for (int q = 0; q < 4; q++) Ws[buf][lc + q][lr] = a[q];
            }
            __syncthreads();
        }
    }

    // epilogue: bias + store 2 rows x 4 cols
    float4 bv = *(const float4*)&b[bm + 4 * tx];
#pragma unroll
    for (int r = 0; r < 2; r++) {
        float4 o;
        o.x = lo32(acc[r][0]) + bv.x;
        o.y = hi32(acc[r][0]) + bv.y;
        o.z = lo32(acc[r][1]) + bv.z;
        o.w = hi32(acc[r][1]) + bv.w;
        *(float4*)&g_feat[(bn + 2 * ty + r) * MM + bm + 4 * tx] = o;
    }
}

// ---------------------------------------------------------------------------
// Kernel 2: pairwise L1 + exp, fused with x -> out copy.
// Grid (64 k, 8 i-tiles of 64) = 512 blocks, 256 threads.
// Warp-level j-slicing: warp w handles j in [ (w&3)*128, +128 ), lanes carry
// distinct i -> all sNeg reads are warp-broadcast (conflict-free).
// Cross-slice reduction through padded smem.
// ---------------------------------------------------------------------------
__global__ __launch_bounds__(256)
void pairwise_kernel(const float* __restrict__ x, float* __restrict__ out) {
    __shared__ __align__(16) ull sNeg[NROWS * 8];   // 32 KB: -feat[:,k,:] packed
    __shared__ float sRed[64][5];                   // padded: conflict-free

    const int k   = blockIdx.x;
    const int i0  = blockIdx.y * 64;
    const int tid = threadIdx.x;

    // Fused copy: x -> out[:, 0:512]. 65536 float4 over 512 blocks.
    {
        const int bid = blockIdx.y * KK + blockIdx.x;   // 0..511
        if (tid < 128) {
            int idx = bid * 128 + tid;                  // 0..65535
            ((float4*)out)[(idx >> 7) * 144 + (idx & 127)] =
                ((const float4*)x)[idx];
        }
    }

    // Load slab: NEGATED feat[:, k, :] packed as f32x2.
    for (int idx = tid; idx < NROWS * 4; idx += 256) {
        int j = idx >> 2;
        int c = (idx & 3) * 4;
        float4 v = *(const float4*)&g_feat[j * MM + k * DD + c];
        sNeg[j * 8 + (c >> 1) + 0] = pk2(-v.x, -v.y);
        sNeg[j * 8 + (c >> 1) + 1] = pk2(-v.z, -v.w);
    }
    __syncthreads();

    const int lane  = tid & 31;
    const int w     = tid >> 5;       // 0..7
    const int slice = w & 3;          // j-slice
    const int ig    = w >> 2;         // i-group 0/1
    const int ii    = ig * 32 + lane; // 0..63 within tile
    const int i     = i0 + ii;

    ull fi[8];
    {
        const float4* p = (const float4*)&g_feat[i * MM + k * DD];
#pragma unroll
        for (int q = 0; q < 4; q++) {
            float4 v = p[q];
            fi[q * 2 + 0] = pk2(v.x, v.y);
            fi[q * 2 + 1] = pk2(v.z, v.w);
        }
    }

    const ull ABSM = 0x7fffffff7fffffffULL;
    float total0 = 0.f, total1 = 0.f;
    const int jb = slice * 128;

#pragma unroll 2
    for (int jj = 0; jj < 128; jj += 2) {
        const int j = jb + jj;
        const ulonglong2* rowA = (const ulonglong2*)&sNeg[j * 8];
        const ulonglong2* rowB = (const ulonglong2*)&sNeg[j * 8 + 8];
        ulonglong2 a0 = rowA[0], a1 = rowA[1], a2 = rowA[2], a3 = rowA[3];
        ulonglong2 b0 = rowB[0], b1 = rowB[1], b2 = rowB[2], b3 = rowB[3];

        ull dA0 = addf32x2(fi[0], a0.x) & ABSM;
        ull dA1 = addf32x2(fi[1], a0.y) & ABSM;
        ull dA2 = addf32x2(fi[2], a1.x) & ABSM;
        ull dA3 = addf32x2(fi[3], a1.y) & ABSM;
        ull dA4 = addf32x2(fi[4], a2.x) & ABSM;
        ull dA5 = addf32x2(fi[5], a2.y) & ABSM;
        ull dA6 = addf32x2(fi[6], a3.x) & ABSM;
        ull dA7 = addf32x2(fi[7], a3.y) & ABSM;
        ull sA = addf32x2(addf32x2(addf32x2(dA0, dA1), addf32x2(dA2, dA3)),
                          addf32x2(addf32x2(dA4, dA5), addf32x2(dA6, dA7)));
        float normA = lo32(sA) + hi32(sA);

        ull dB0 = addf32x2(fi[0], b0.x) & ABSM;
        ull dB1 = addf32x2(fi[1], b0.y) & ABSM;
        ull dB2 = addf32x2(fi[2], b1.x) & ABSM;
        ull dB3 = addf32x2(fi[3], b1.y) & ABSM;
        ull dB4 = addf32x2(fi[4], b2.x) & ABSM;
        ull dB5 = addf32x2(fi[5], b2.y) & ABSM;
        ull dB6 = addf32x2(fi[6], b3.x) & ABSM;
        ull dB7 = addf32x2(fi[7], b3.y) & ABSM;
        ull sB = addf32x2(addf32x2(addf32x2(dB0, dB1), addf32x2(dB2, dB3)),
                          addf32x2(addf32x2(dB4, dB5), addf32x2(dB6, dB7)));
        float normB = lo32(sB) + hi32(sB);

        float eA = __expf(-normA);
        float eB = __expf(-normB);
        total0 += (j     == i) ? 0.f : eA;
        total1 += (j + 1 == i) ? 0.f : eB;
    }

    sRed[ii][slice] = total0 + total1;
    __syncthreads();

    if (tid < 64) {
        float t = sRed[tid][0] + sRed[tid][1] + sRed[tid][2] + sRed[tid][3];
        out[(i0 + tid) * OUTW + INSIZE + k] = t;
    }
}

// ---------------------------------------------------------------------------
extern "C" void kernel_launch(void* const* d_in, const int* in_sizes, int n_in,
                              void* d_out, int out_size) {
    const float* x = (const float*)d_in[0];   // [512,512]
    const float* W = (const float*)d_in[1];   // [1024,512]
    const float* b = (const float*)d_in[2];   // [1024]
    float* out = (float*)d_out;               // [512,576]

    dim3 ggrid(MM / 64, NROWS / 64);          // (16, 8) = 128 blocks
    gemm_kernel<<<ggrid, 512>>>(x, W, b);

    dim3 pgrid(KK, NROWS / 64);               // (64, 8) = 512 blocks
    pairwise_kernel<<<pgrid, 256>>>(x, out);
}

// round 5
// speedup vs baseline: 1.2190x; 1.2190x over previous
#include <cuda_runtime.h>
#include <cstdint>

#define NROWS  512
#define INSIZE 512
#define KK     64
#define DD     16
#define MM     (KK * DD)        // 1024
#define OUTW   (INSIZE + KK)    // 576
#define BK     16

typedef unsigned long long ull;

// Split-K partial results of x @ W^T, stored K-MAJOR: [k][row][d] (64x512x16)
__device__ float g_A[NROWS * MM];
__device__ float g_B[NROWS * MM];

// ---------------------------------------------------------------------------
// Packed f32x2 helpers
// ---------------------------------------------------------------------------
__device__ __forceinline__ ull addf32x2(ull a, ull b) {
    ull r;
    asm("add.rn.f32x2 %0, %1, %2;" : "=l"(r) : "l"(a), "l"(b));
    return r;
}
__device__ __forceinline__ ull fmaf32x2(ull a, ull b, ull c) {
    ull r;
    asm("fma.rn.f32x2 %0, %1, %2, %3;" : "=l"(r) : "l"(a), "l"(b), "l"(c));
    return r;
}
__device__ __forceinline__ ull pk2(float lo, float hi) {
    ull r;
    asm("mov.b64 %0, {%1, %2};" : "=l"(r)
        : "r"(__float_as_uint(lo)), "r"(__float_as_uint(hi)));
    return r;
}
__device__ __forceinline__ float lo32(ull v) {
    return __uint_as_float((unsigned int)v);
}
__device__ __forceinline__ float hi32(ull v) {
    return __uint_as_float((unsigned int)(v >> 32));
}
__device__ __forceinline__ float ex2f(float v) {
    float r;
    asm("ex2.approx.f32 %0, %1;" : "=f"(r) : "f"(v));
    return r;
}

#define NLOG2E (-1.4426950408889634f)

// ---------------------------------------------------------------------------
// Kernel 1: split-K GEMM partials. grid (16 m-tiles, 8 n-tiles, 2 k-halves),
// 256 threads, 64x64 tile, 4x4 micro-tile with packed FFMA2, double-buffered.
// blockIdx.z=0 -> k[0,256) -> g_A ; z=1 -> k[256,512) -> g_B. No bias here.
// Output K-MAJOR: dst[(col>>4)*(512*16) + row*16 + (col&15)].
// ---------------------------------------------------------------------------
__global__ __launch_bounds__(256)
void gemm_kernel(const float* __restrict__ x, const float* __restrict__ W) {
    __shared__ __align__(16) float XsD[2][BK][128];  // duplicated x rows: 16KB
    __shared__ __align__(16) float Ws [2][BK][64];   // 8KB

    const int bm = blockIdx.x * 64;       // feat col tile
    const int bn = blockIdx.y * 64;       // row tile
    const int kbase = blockIdx.z * 256;   // k half
    float* dst = blockIdx.z ? g_B : g_A;

    const int tid = threadIdx.x;
    const int lr = tid >> 2;              // 0..63
    const int lc = (tid & 3) * 4;         // 0,4,8,12
    const int tx = tid & 15;              // cols 4tx..4tx+3
    const int ty = tid >> 4;              // rows 4ty..4ty+3

    const float* xg = &x[(bn + lr) * INSIZE + kbase + lc];
    const float* wg = &W[(bm + lr) * INSIZE + kbase + lc];

    ull acc[4][2];
#pragma unroll
    for (int r = 0; r < 4; r++) { acc[r][0] = 0ULL; acc[r][1] = 0ULL; }

    int buf = 0;
    {
        float4 xv = *(const float4*)xg;
        float4 wv = *(const float4*)wg;
        float xa[4] = {xv.x, xv.y, xv.z, xv.w};
        float wa[4] = {wv.x, wv.y, wv.z, wv.w};
#pragma unroll
        for (int q = 0; q < 4; q++) {
            *(float2*)&XsD[buf][lc + q][2 * lr] = make_float2(xa[q], xa[q]);
            Ws[buf][lc + q][lr] = wa[q];
        }
    }
    __syncthreads();

    for (int step = 1; step <= 16; step++) {
        const bool more = (step < 16);
        float4 xv2, wv2;
        if (more) {
            xv2 = *(const float4*)(xg + step * BK);
            wv2 = *(const float4*)(wg + step * BK);
        }

#pragma unroll
        for (int kk = 0; kk < BK; kk++) {
            ulonglong2 xp = *(const ulonglong2*)&XsD[buf][kk][8 * ty];      // (r0,r0),(r1,r1)
            ulonglong2 xq = *(const ulonglong2*)&XsD[buf][kk][8 * ty + 4];  // (r2,r2),(r3,r3)
            ulonglong2 wp = *(const ulonglong2*)&Ws [buf][kk][4 * tx];
            acc[0][0] = fmaf32x2(xp.x, wp.x, acc[0][0]);
            acc[0][1] = fmaf32x2(xp.x, wp.y, acc[0][1]);
            acc[1][0] = fmaf32x2(xp.y, wp.x, acc[1][0]);
            acc[1][1] = fmaf32x2(xp.y, wp.y, acc[1][1]);
            acc[2][0] = fmaf32x2(xq.x, wp.x, acc[2][0]);
            acc[2][1] = fmaf32x2(xq.x, wp.y, acc[2][1]);
            acc[3][0] = fmaf32x2(xq.y, wp.x, acc[3][0]);
            acc[3][1] = fmaf32x2(xq.y, wp.y, acc[3][1]);
        }

        if (more) {
            buf ^= 1;
            float xa[4] = {xv2.x, xv2.y, xv2.z, xv2.w};
            float wa[4] = {wv2.x, wv2.y, wv2.z, wv2.w};
#pragma unroll
            for (int q = 0; q < 4; q++) {
                *(float2*)&XsD[buf][lc + q][2 * lr] = make_float2(xa[q], xa[q]);
                Ws[buf][lc + q][lr] = wa[q];
            }
            __syncthreads();
        }
    }

    // epilogue: store K-MAJOR (4 cols of one thread lie within one k-group)
    const int col = bm + 4 * tx;
    float* base = dst + (col >> 4) * (NROWS * DD) + (col & 15);
#pragma unroll
    for (int r = 0; r < 4; r++) {
        float4 o;
        o.x = lo32(acc[r][0]);
        o.y = hi32(acc[r][0]);
        o.z = lo32(acc[r][1]);
        o.w = hi32(acc[r][1]);
        *(float4*)&base[(bn + 4 * ty + r) * DD] = o;
    }
}

// ---------------------------------------------------------------------------
// Kernel 2: pairwise L1 + exp (packed abs-diff tree), fused x -> out copy.
// Grid (64 k, 16 i-tiles of 32) = 1024 blocks, 256 thr.
// Warp w handles j-slice [w*64, +64); lanes = 32 i's; slab reads broadcast.
// Slab holds NEGATED feat so diff is one packed add. Diagonal: |d|=0 ->
// exp = 1 exactly, subtract 1.0 after reduction (no per-row select).
// ---------------------------------------------------------------------------
__global__ __launch_bounds__(256)
void pairwise_kernel(const float* __restrict__ x, const float* __restrict__ b,
                     float* __restrict__ out) {
    __shared__ __align__(16) ull sNeg[NROWS * 8];   // 32 KB: -feat[:,k,:]
    __shared__ float sRed[32][9];

    const int k   = blockIdx.x;
    const int i0  = blockIdx.y * 32;
    const int tid = threadIdx.x;

    // fused copy: x -> out[:, 0:512]; 65536 float4 over 1024 blocks
    {
        const int bid = blockIdx.y * KK + blockIdx.x;   // 0..1023
        if (tid < 64) {
            int idx = bid * 64 + tid;
            ((float4*)out)[(idx >> 7) * 144 + (idx & 127)] =
                ((const float4*)x)[idx];
        }
    }

    // assemble slab = -(g_A + g_B + bias), coalesced K-major float4 reads
    {
        const float4* A4 = (const float4*)(g_A + k * (NROWS * DD));
        const float4* B4 = (const float4*)(g_B + k * (NROWS * DD));
        float4 bb = *(const float4*)&b[k * DD + (tid & 3) * 4];
        float2* s2 = (float2*)sNeg;
#pragma unroll
        for (int it = 0; it < 8; it++) {
            int idx = tid + it * 256;
            float4 va = A4[idx], vb = B4[idx];
            s2[idx * 2 + 0] = make_float2(-(va.x + vb.x + bb.x),
                                          -(va.y + vb.y + bb.y));
            s2[idx * 2 + 1] = make_float2(-(va.z + vb.z + bb.z),
                                          -(va.w + vb.w + bb.w));
        }
    }
    __syncthreads();

    const int lane = tid & 31;
    const int w    = tid >> 5;        // 0..7 -> j-slice
    const int i    = i0 + lane;

    // own row (positive) = -slab[i]
    ull fi[8];
    {
        const ulonglong2* p = (const ulonglong2*)&sNeg[i * 8];
        ulonglong2 f0 = p[0], f1 = p[1], f2 = p[2], f3 = p[3];
        ull nf[8] = {f0.x, f0.y, f1.x, f1.y, f2.x, f2.y, f3.x, f3.y};
#pragma unroll
        for (int q = 0; q < 8; q++)
            fi[q] = pk2(-lo32(nf[q]), -hi32(nf[q]));
    }

    const ull ABSM = 0x7fffffff7fffffffULL;
    float tot0 = 0.f, tot1 = 0.f;
    const int jb = w * 64;

#pragma unroll 2
    for (int jj = 0; jj < 64; jj += 2) {
        const int j = jb + jj;
        const ulonglong2* rowA = (const ulonglong2*)&sNeg[j * 8];
        const ulonglong2* rowB = (const ulonglong2*)&sNeg[j * 8 + 8];
        ulonglong2 a0 = rowA[0], a1 = rowA[1], a2 = rowA[2], a3 = rowA[3];
        ulonglong2 b0 = rowB[0], b1 = rowB[1], b2 = rowB[2], b3 = rowB[3];

        ull dA0 = addf32x2(fi[0], a0.x) & ABSM;
        ull dA1 = addf32x2(fi[1], a0.y) & ABSM;
        ull dA2 = addf32x2(fi[2], a1.x) & ABSM;
        ull dA3 = addf32x2(fi[3], a1.y) & ABSM;
        ull dA4 = addf32x2(fi[4], a2.x) & ABSM;
        ull dA5 = addf32x2(fi[5], a2.y) & ABSM;
        ull dA6 = addf32x2(fi[6], a3.x) & ABSM;
        ull dA7 = addf32x2(fi[7], a3.y) & ABSM;
        ull sA = addf32x2(addf32x2(addf32x2(dA0, dA1), addf32x2(dA2, dA3)),
                          addf32x2(addf32x2(dA4, dA5), addf32x2(dA6, dA7)));
        tot0 += ex2f((lo32(sA) + hi32(sA)) * NLOG2E);

        ull dB0 = addf32x2(fi[0], b0.x) & ABSM;
        ull dB1 = addf32x2(fi[1], b0.y) & ABSM;
        ull dB2 = addf32x2(fi[2], b1.x) & ABSM;
        ull dB3 = addf32x2(fi[3], b1.y) & ABSM;
        ull dB4 = addf32x2(fi[4], b2.x) & ABSM;
        ull dB5 = addf32x2(fi[5], b2.y) & ABSM;
        ull dB6 = addf32x2(fi[6], b3.x) & ABSM;
        ull dB7 = addf32x2(fi[7], b3.y) & ABSM;
        ull sB = addf32x2(addf32x2(addf32x2(dB0, dB1), addf32x2(dB2, dB3)),
                          addf32x2(addf32x2(dB4, dB5), addf32x2(dB6, dB7)));
        tot1 += ex2f((lo32(sB) + hi32(sB)) * NLOG2E);
    }

    sRed[lane][w] = tot0 + tot1;
    __syncthreads();

    if (tid < 32) {
        float t = 0.f;
#pragma unroll
        for (int s = 0; s < 8; s++) t += sRed[tid][s];
        out[(i0 + tid) * OUTW + INSIZE + k] = t - 1.0f;  // remove diagonal
    }
}

// ---------------------------------------------------------------------------
extern "C" void kernel_launch(void* const* d_in, const int* in_sizes, int n_in,
                              void* d_out, int out_size) {
    const float* x = (const float*)d_in[0];   // [512,512]
    const float* W = (const float*)d_in[1];   // [1024,512]
    const float* b = (const float*)d_in[2];   // [1024]
    float* out = (float*)d_out;               // [512,576]

    dim3 ggrid(MM / 64, NROWS / 64, 2);       // (16, 8, 2) = 256 blocks
    gemm_kernel<<<ggrid, 256>>>(x, W);

    dim3 pgrid(KK, NROWS / 32);               // (64, 16) = 1024 blocks
    pairwise_kernel<<<pgrid, 256>>>(x, b, out);
}

// round 6
// speedup vs baseline: 1.3056x; 1.0710x over previous
#include <cuda_runtime.h>
#include <cstdint>

#define NROWS  512
#define INSIZE 512
#define KK     64
#define DD     16
#define MM     (KK * DD)        // 1024
#define OUTW   (INSIZE + KK)    // 576
#define BK     16
#define T      64               // pairwise tile size
#define PART   (NROWS * MM)     // one split-K partial, K-major [k][row][d]
#define PARTO  (NROWS * KK)     // one output-slot partial [k][i]

typedef unsigned long long ull;

// 4 split-K partials of x @ W^T, K-major: [k][row][d]
__device__ float g_P[4 * PART];          // 8 MB
// 8 output slots: g_part[slot][k][i]
__device__ float g_part[8 * PARTO];      // 1 MB

// ---------------------------------------------------------------------------
// Packed f32x2 helpers
// ---------------------------------------------------------------------------
__device__ __forceinline__ ull addf32x2(ull a, ull b) {
    ull r;
    asm("add.rn.f32x2 %0, %1, %2;" : "=l"(r) : "l"(a), "l"(b));
    return r;
}
__device__ __forceinline__ ull fmaf32x2(ull a, ull b, ull c) {
    ull r;
    asm("fma.rn.f32x2 %0, %1, %2, %3;" : "=l"(r) : "l"(a), "l"(b), "l"(c));
    return r;
}
__device__ __forceinline__ float lo32(ull v) {
    return __uint_as_float((unsigned int)v);
}
__device__ __forceinline__ float hi32(ull v) {
    return __uint_as_float((unsigned int)(v >> 32));
}
__device__ __forceinline__ float ex2f(float v) {
    float r;
    asm("ex2.approx.f32 %0, %1;" : "=f"(r) : "f"(v));
    return r;
}

#define NLOG2E (-1.4426950408889634f)

// ---------------------------------------------------------------------------
// Kernel 1: split-K(4) GEMM partials. grid (16 m-tiles, 8 n-tiles, 4 k-quarters),
// 256 threads, 64x64 tile, 4x4 micro-tile packed FFMA2, double-buffered.
// Output K-MAJOR into g_P[z]: dst[(col>>4)*(512*16) + row*16 + (col&15)].
// ---------------------------------------------------------------------------
__global__ __launch_bounds__(256)
void gemm_kernel(const float* __restrict__ x, const float* __restrict__ W) {
    __shared__ __align__(16) float XsD[2][BK][128];  // duplicated x rows
    __shared__ __align__(16) float Ws [2][BK][64];

    const int bm = blockIdx.x * 64;
    const int bn = blockIdx.y * 64;
    const int kbase = blockIdx.z * 128;       // k quarter
    float* dst = g_P + blockIdx.z * PART;

    const int tid = threadIdx.x;
    const int lr = tid >> 2;
    const int lc = (tid & 3) * 4;
    const int tx = tid & 15;
    const int ty = tid >> 4;

    const float* xg = &x[(bn + lr) * INSIZE + kbase + lc];
    const float* wg = &W[(bm + lr) * INSIZE + kbase + lc];

    ull acc[4][2];
#pragma unroll
    for (int r = 0; r < 4; r++) { acc[r][0] = 0ULL; acc[r][1] = 0ULL; }

    int buf = 0;
    {
        float4 xv = *(const float4*)xg;
        float4 wv = *(const float4*)wg;
        float xa[4] = {xv.x, xv.y, xv.z, xv.w};
        float wa[4] = {wv.x, wv.y, wv.z, wv.w};
#pragma unroll
        for (int q = 0; q < 4; q++) {
            *(float2*)&XsD[buf][lc + q][2 * lr] = make_float2(xa[q], xa[q]);
            Ws[buf][lc + q][lr] = wa[q];
        }
    }
    __syncthreads();

    for (int step = 1; step <= 8; step++) {
        const bool more = (step < 8);
        float4 xv2, wv2;
        if (more) {
            xv2 = *(const float4*)(xg + step * BK);
            wv2 = *(const float4*)(wg + step * BK);
        }

#pragma unroll
        for (int kk = 0; kk < BK; kk++) {
            ulonglong2 xp = *(const ulonglong2*)&XsD[buf][kk][8 * ty];
            ulonglong2 xq = *(const ulonglong2*)&XsD[buf][kk][8 * ty + 4];
            ulonglong2 wp = *(const ulonglong2*)&Ws [buf][kk][4 * tx];
            acc[0][0] = fmaf32x2(xp.x, wp.x, acc[0][0]);
            acc[0][1] = fmaf32x2(xp.x, wp.y, acc[0][1]);
            acc[1][0] = fmaf32x2(xp.y, wp.x, acc[1][0]);
            acc[1][1] = fmaf32x2(xp.y, wp.y, acc[1][1]);
            acc[2][0] = fmaf32x2(xq.x, wp.x, acc[2][0]);
            acc[2][1] = fmaf32x2(xq.x, wp.y, acc[2][1]);
            acc[3][0] = fmaf32x2(xq.y, wp.x, acc[3][0]);
            acc[3][1] = fmaf32x2(xq.y, wp.y, acc[3][1]);
        }

        if (more) {
            buf ^= 1;
            float xa[4] = {xv2.x, xv2.y, xv2.z, xv2.w};
            float wa[4] = {wv2.x, wv2.y, wv2.z, wv2.w};
#pragma unroll
            for (int q = 0; q < 4; q++) {
                *(float2*)&XsD[buf][lc + q][2 * lr] = make_float2(xa[q], xa[q]);
                Ws[buf][lc + q][lr] = wa[q];
            }
            __syncthreads();
        }
    }

    const int col = bm + 4 * tx;
    float* base = dst + (col >> 4) * (NROWS * DD) + (col & 15);
#pragma unroll
    for (int r = 0; r < 4; r++) {
        float4 o;
        o.x = lo32(acc[r][0]);
        o.y = hi32(acc[r][0]);
        o.z = lo32(acc[r][1]);
        o.w = hi32(acc[r][1]);
        *(float4*)&base[(bn + 4 * ty + r) * DD] = o;
    }
}

// ---------------------------------------------------------------------------
// Kernel 2: symmetric pairwise L1 + exp over 64x64 tile-pairs.
// grid (64 k, 36 units): unit<8 -> diagonal tile (full ordered 64x64, i-role
// only); unit>=8 -> upper-triangle pair (a<b): each e(i,j) feeds per-lane
// tot_i AND an e-matrix in smem whose columns reduce to tot_j.
// Writes disjoint slots of g_part (no atomics, deterministic).
// 256 threads = 8 warps: h=w>>2 picks i-half (32 lanes = 32 i), s=w&3 picks
// 16-row j-slice. Stripe A stored positive, stripe B negated.
// ---------------------------------------------------------------------------
__global__ __launch_bounds__(256)
void pairwise_kernel(const float* __restrict__ b) {
    __shared__ __align__(16) ull sA[T * 8];        // 4 KB, +feat tile a
    __shared__ __align__(16) ull sB[T * 8];        // 4 KB, -feat tile b
    __shared__ float sE[2 * T * 33];               // e-matrix, pad 33
    __shared__ float sTot[8][32];                  // per-warp tot_i partials

    const int k = blockIdx.x;
    int u = blockIdx.y;
    int a, bt;
    if (u < 8) { a = u; bt = u; }
    else {
        int v = u - 8;
        a = 0;
        while (v >= 7 - a) { v -= 7 - a; a++; }
        bt = a + 1 + v;
    }
    const bool diag = (a == bt);
    const int tid = threadIdx.x;

    // stripe assembly: one float4 per thread per stripe (64 rows x 4 quads)
    {
        const int row = tid >> 2;
        const int c4 = tid & 3;
        const float* base = g_P + k * (NROWS * DD) + c4 * 4;
        float4 bias4 = *(const float4*)&b[k * DD + c4 * 4];

        const float* pa = base + (a * T + row) * DD;
        float4 v0 = *(const float4*)pa;
        float4 v1 = *(const float4*)(pa + PART);
        float4 v2 = *(const float4*)(pa + 2 * PART);
        float4 v3 = *(const float4*)(pa + 3 * PART);
        float ax = v0.x + v1.x + v2.x + v3.x + bias4.x;
        float ay = v0.y + v1.y + v2.y + v3.y + bias4.y;
        float az = v0.z + v1.z + v2.z + v3.z + bias4.z;
        float aw = v0.w + v1.w + v2.w + v3.w + bias4.w;
        ((float2*)sA)[row * 8 + c4 * 2]     = make_float2(ax, ay);
        ((float2*)sA)[row * 8 + c4 * 2 + 1] = make_float2(az, aw);

        const float* pb = base + (bt * T + row) * DD;
        float4 w0 = *(const float4*)pb;
        float4 w1 = *(const float4*)(pb + PART);
        float4 w2 = *(const float4*)(pb + 2 * PART);
        float4 w3 = *(const float4*)(pb + 3 * PART);
        float bx = w0.x + w1.x + w2.x + w3.x + bias4.x;
        float by = w0.y + w1.y + w2.y + w3.y + bias4.y;
        float bz = w0.z + w1.z + w2.z + w3.z + bias4.z;
        float bw = w0.w + w1.w + w2.w + w3.w + bias4.w;
        ((float2*)sB)[row * 8 + c4 * 2]     = make_float2(-bx, -by);
        ((float2*)sB)[row * 8 + c4 * 2 + 1] = make_float2(-bz, -bw);
    }
    __syncthreads();

    const int lane = tid & 31;
    const int w    = tid >> 5;
    const int h    = w >> 2;          // i-half
    const int s    = w & 3;           // j-slice
    const int iL   = h * 32 + lane;   // local i in tile a

    ull fi[8];
    {
        const ulonglong2* p = (const ulonglong2*)&sA[iL * 8];
        ulonglong2 f0 = p[0], f1 = p[1], f2 = p[2], f3 = p[3];
        fi[0] = f0.x; fi[1] = f0.y; fi[2] = f1.x; fi[3] = f1.y;
        fi[4] = f2.x; fi[5] = f2.y; fi[6] = f3.x; fi[7] = f3.y;
    }

    const ull ABSM = 0x7fffffff7fffffffULL;
    const int hbase = h * (T * 33);
    float totI = 0.f;
    const int jb = s * 16;

#pragma unroll 4
    for (int jj = 0; jj < 16; jj++) {
        const int j = jb + jj;
        const ulonglong2* row = (const ulonglong2*)&sB[j * 8];
        ulonglong2 q0 = row[0], q1 = row[1], q2 = row[2], q3 = row[3];

        ull d0 = addf32x2(fi[0], q0.x) & ABSM;
        ull d1 = addf32x2(fi[1], q0.y) & ABSM;
        ull d2 = addf32x2(fi[2], q1.x) & ABSM;
        ull d3 = addf32x2(fi[3], q1.y) & ABSM;
        ull d4 = addf32x2(fi[4], q2.x) & ABSM;
        ull d5 = addf32x2(fi[5], q2.y) & ABSM;
        ull d6 = addf32x2(fi[6], q3.x) & ABSM;
        ull d7 = addf32x2(fi[7], q3.y) & ABSM;
        ull sm = addf32x2(addf32x2(addf32x2(d0, d1), addf32x2(d2, d3)),
                          addf32x2(addf32x2(d4, d5), addf32x2(d6, d7)));
        float e = ex2f((lo32(sm) + hi32(sm)) * NLOG2E);
        totI += e;
        if (!diag) sE[hbase + j * 33 + lane] = e;
    }

    sTot[w][lane] = totI;
    __syncthreads();

    if (tid < 64) {
        // tot_i for local i = tid : sum the 4 j-slices of this half
        const int hh = tid >> 5, l = tid & 31;
        float t = sTot[hh * 4 + 0][l] + sTot[hh * 4 + 1][l] +
                  sTot[hh * 4 + 2][l] + sTot[hh * 4 + 3][l];
        g_part[bt * PARTO + k * NROWS + a * T + tid] = t;
    } else if (!diag && tid < 128) {
        // tot_j for local j = tid-64 : sum e over 64 i (2 halves x 32 lanes)
        const int jL = tid - 64;
        float t = 0.f;
        const float* e0 = &sE[jL * 33];
        const float* e1 = &sE[T * 33 + jL * 33];
#pragma unroll
        for (int l = 0; l < 32; l++) t += e0[l] + e1[l];
        g_part[a * PARTO + k * NROWS + bt * T + jL] = t;
    }
}

// ---------------------------------------------------------------------------
// Kernel 3: finalize. out[:,512+k] = sum_slots g_part - 1 (diagonal), plus
// x -> out[:,0:512] copy. grid (64 k-blocks) x 512 threads (one i each).
// ---------------------------------------------------------------------------
__global__ __launch_bounds__(512)
void final_kernel(const float* __restrict__ x, float* __restrict__ out) {
    const int k = blockIdx.x;
    const int i = threadIdx.x;

    float t = -1.0f;
#pragma unroll
    for (int p = 0; p < 8; p++) t += g_part[p * PARTO + k * NROWS + i];
    out[i * OUTW + INSIZE + k] = t;

    // x copy: 2 float4 per thread
    const float4* xin = (const float4*)x;
    float4* o4 = (float4*)out;
#pragma unroll
    for (int v = 0; v < 2; v++) {
        int idx = (k * 512 + i) * 2 + v;          // 0..65535
        o4[(idx >> 7) * 144 + (idx & 127)] = xin[idx];
    }
}

// ---------------------------------------------------------------------------
extern "C" void kernel_launch(void* const* d_in, const int* in_sizes, int n_in,
                              void* d_out, int out_size) {
    const float* x = (const float*)d_in[0];   // [512,512]
    const float* W = (const float*)d_in[1];   // [1024,512]
    const float* b = (const float*)d_in[2];   // [1024]
    float* out = (float*)d_out;               // [512,576]

    dim3 ggrid(MM / 64, NROWS / 64, 4);       // (16, 8, 4) = 512 blocks
    gemm_kernel<<<ggrid, 256>>>(x, W);

    dim3 pgrid(KK, 36);                       // 2304 tile-pair blocks
    pairwise_kernel<<<pgrid, 256>>>(b);

    final_kernel<<<KK, 512>>>(x, out);
}